// round 10
// baseline (speedup 1.0000x reference)
#include <cuda_runtime.h>
#include <cuda_bf16.h>
#include <math.h>
#include <stdint.h>

// Problem constants
#define KK    64
#define DD    512
#define TT    128
#define BB    512
#define BOS_T 63
#define EOS_T 62
#define LOG64 4.158883083359672f
#define STR   68              // padded SMEM row stride in 4B words (272B)

// Emission probabilities exp(wb)/64 (cols 62,63 zeroed): [seq][t][k] f32 = 16 MB
__device__ float g_swb[(size_t)BB * TT * KK];

__device__ __forceinline__ uint32_t pk(float a, float b) {
    __nv_bfloat162 h = __floats2bfloat162_rn(a, b);
    return *reinterpret_cast<uint32_t*>(&h);
}

__device__ __forceinline__ void mma16816(float* c, uint32_t a0, uint32_t a1,
                                         uint32_t a2, uint32_t a3,
                                         uint32_t b0, uint32_t b1) {
    asm volatile(
        "mma.sync.aligned.m16n8k16.row.col.f32.bf16.bf16.f32 "
        "{%0,%1,%2,%3}, {%4,%5,%6,%7}, {%8,%9}, {%0,%1,%2,%3};"
        : "+f"(c[0]), "+f"(c[1]), "+f"(c[2]), "+f"(c[3])
        : "r"(a0), "r"(a1), "r"(a2), "r"(a3), "r"(b0), "r"(b1));
}

__device__ __forceinline__ void ldsm4(uint32_t& r0, uint32_t& r1,
                                      uint32_t& r2, uint32_t& r3, uint32_t addr) {
    asm volatile("ldmatrix.sync.aligned.m8n8.x4.shared.b16 {%0,%1,%2,%3}, [%4];"
                 : "=r"(r0), "=r"(r1), "=r"(r2), "=r"(r3) : "r"(addr));
}

// ---------------------------------------------------------------------------
// Kernel 1: emission. blk = base + blockIdx.x -> (seq b, t-half h).
// M=64 t-rows x N=64 tags, K=512 in 4 chunks of 128.
// Register-prefetched E gather; ldmatrix fragment loads; writes exp(wb)/64.
// ---------------------------------------------------------------------------
__global__ __launch_bounds__(256, 3)
void emit_kernel(int base,
                 const float* __restrict__ ThetaB,
                 const float* __restrict__ E,
                 const int*   __restrict__ words)
{
    __shared__ uint32_t A32[64 * STR];
    __shared__ uint32_t B32[64 * STR];

    const int blk = base + blockIdx.x;
    const int b = blk >> 1, h = blk & 1;
    const int tid  = threadIdx.x;
    const int wid  = tid >> 5, lane = tid & 31;
    const int g    = lane >> 2, t4 = lane & 3;
    const int mt = wid & 3, nh = wid >> 2;
    const int m0 = mt * 16;

    // gather: 4 threads per row, 32 f32 (8 float4) per chunk each
    const int row = tid >> 2, q = tid & 3;
    const int word = words[b * TT + h * 64 + row];
    const float4* eptr = (const float4*)(E + (size_t)word * DD + q * 32);
    const float4* tptr = (const float4*)(ThetaB + row * DD + q * 32);

    // ldmatrix source addresses (shared-state-space u32)
    const uint32_t Abase = (uint32_t)__cvta_generic_to_shared(A32);
    const uint32_t Bbase = (uint32_t)__cvta_generic_to_shared(B32);
    const uint32_t aA  = Abase + (uint32_t)((m0 + (lane & 15)) * 272
                       + ((lane >> 4) & 1) * 16);
    const uint32_t aB0 = Bbase + (uint32_t)((nh * 32 + ((lane >> 4) & 1) * 8
                       + (lane & 7)) * 272 + ((lane >> 3) & 1) * 16);
    const uint32_t aB1 = aB0 + 16 * 272;

    float acc[4][4];
#pragma unroll
    for (int nt = 0; nt < 4; ++nt)
#pragma unroll
        for (int r = 0; r < 4; ++r) acc[nt][r] = 0.f;

    // prefetch E chunk 0
    float4 er[8];
#pragma unroll
    for (int j = 0; j < 8; ++j) er[j] = eptr[j];

    for (int c = 0; c < 4; ++c) {
        if (c) __syncthreads();                  // MMA of c-1 done, SMEM free

        // store A (from prefetched regs) + load/convert/store Theta chunk c
#pragma unroll
        for (int j = 0; j < 4; ++j) {
            float4 f0 = er[2 * j], f1 = er[2 * j + 1];
            *(uint4*)((char*)A32 + row * 272 + q * 64 + j * 16) =
                make_uint4(pk(f0.x, f0.y), pk(f0.z, f0.w), pk(f1.x, f1.y), pk(f1.z, f1.w));
        }
        {
            const float4* t4p = tptr + c * 32;
#pragma unroll
            for (int j = 0; j < 4; ++j) {
                float4 g0 = t4p[2 * j], g1 = t4p[2 * j + 1];
                *(uint4*)((char*)B32 + row * 272 + q * 64 + j * 16) =
                    make_uint4(pk(g0.x, g0.y), pk(g0.z, g0.w), pk(g1.x, g1.y), pk(g1.z, g1.w));
            }
        }
        __syncthreads();

        // prefetch next E chunk (overlaps with MMA below)
        if (c < 3) {
            const float4* en = eptr + (c + 1) * 32;
#pragma unroll
            for (int j = 0; j < 8; ++j) er[j] = en[j];
        }

        // MMA: 8 k16-steps, ldmatrix fragment loads
#pragma unroll
        for (int s = 0; s < 8; ++s) {
            uint32_t a0, a1, a2, a3, b0, b1, b2, b3, b4, b5, b6, b7;
            ldsm4(a0, a1, a2, a3, aA + s * 32);
            ldsm4(b0, b1, b2, b3, aB0 + s * 32);
            ldsm4(b4, b5, b6, b7, aB1 + s * 32);
            mma16816(acc[0], a0, a1, a2, a3, b0, b1);
            mma16816(acc[1], a0, a1, a2, a3, b2, b3);
            mma16816(acc[2], a0, a1, a2, a3, b4, b5);
            mma16816(acc[3], a0, a1, a2, a3, b6, b7);
        }
    }

    // epilogue: exp/64, mask cols 62/63, write f32
    const float inv = 1.0f / 64.0f;
    float* obase = g_swb + (size_t)b * TT * KK;
    const int t0 = h * 64 + m0 + g, t1 = t0 + 8;
#pragma unroll
    for (int nt = 0; nt < 4; ++nt) {
        const int col = (nh * 4 + nt) * 8 + t4 * 2;
        const bool msk = (col == EOS_T);
        float2 v0, v1;
        v0.x = msk ? 0.f : __expf(acc[nt][0]) * inv;
        v0.y = msk ? 0.f : __expf(acc[nt][1]) * inv;
        v1.x = msk ? 0.f : __expf(acc[nt][2]) * inv;
        v1.y = msk ? 0.f : __expf(acc[nt][3]) * inv;
        *(float2*)(obase + t0 * KK + col) = v0;
        *(float2*)(obase + t1 * KK + col) = v1;
    }
}

// ---------------------------------------------------------------------------
// Kernel 2: one WARP per sequence (R6 scalar version, known good).
// Stage: pure copy of rows 1..126 (emit already applied exp/64 + mask).
// Each thread owns outputs k=lane and k=lane+32, both A columns in registers.
// ---------------------------------------------------------------------------
__global__ __launch_bounds__(32)
void forward_kernel(const float* __restrict__ WA,
                    const int*   __restrict__ tags,
                    float*       __restrict__ out)
{
    __shared__ __align__(16) float swb_s[126 * KK];   // rows t=1..126
    __shared__ __align__(16) float sal[2][KK];

    const int lane = threadIdx.x;
    const int b    = blockIdx.x;

    // stage: pure copy
    {
        const float4* src = (const float4*)(g_swb + (size_t)b * TT * KK + KK);
        float4* dst = (float4*)swb_s;
        for (int i = lane; i < 126 * 16; i += 32) dst[i] = src[i];
    }

    // A columns for k=lane and k=lane+32 in registers
    float A0[KK], A1[KK];
#pragma unroll
    for (int j = 0; j < KK; ++j) {
        A0[j] = __expf(WA[j * KK + lane]);
        A1[j] = __expf(WA[j * KK + lane + 32]);
    }
    __syncwarp();

    // tagged closed form
    float tagc = 0.f;
    for (int t = lane + 1; t <= 126; t += 32) {
        const int ct = tags[b * TT + t];
        const int pt = (t == 1) ? BOS_T : tags[b * TT + t - 1];
        tagc += __logf(swb_s[(t - 1) * KK + ct]) + LOG64 + WA[pt * KK + ct];
    }
    if (lane == 0) tagc += WA[tags[b * TT + 126] * KK + EOS_T];
#pragma unroll
    for (int o = 16; o > 0; o >>= 1) tagc += __shfl_down_sync(0xffffffffu, tagc, o);
    const float tagged = tagc;                         // valid on lane 0

    // forward recursion
    float a0 = A0[BOS_T] * swb_s[lane];                // t=1 row at offset 0
    float a1 = A1[BOS_T] * swb_s[lane + 32];

    int buf = 0;
    for (int t = 2; t <= 126; ++t) {
        sal[buf][lane] = a0;
        sal[buf][lane + 32] = a1;
        __syncwarp();
        const float4* av = (const float4*)sal[buf];
        float p0a = 0.f, p1a = 0.f, p2a = 0.f, p3a = 0.f;
        float q0a = 0.f, q1a = 0.f, q2a = 0.f, q3a = 0.f;
#pragma unroll
        for (int jj = 0; jj < 16; ++jj) {
            const float4 v = av[jj];
            p0a = fmaf(v.x, A0[4 * jj + 0], p0a);
            p1a = fmaf(v.y, A0[4 * jj + 1], p1a);
            p2a = fmaf(v.z, A0[4 * jj + 2], p2a);
            p3a = fmaf(v.w, A0[4 * jj + 3], p3a);
            q0a = fmaf(v.x, A1[4 * jj + 0], q0a);
            q1a = fmaf(v.y, A1[4 * jj + 1], q1a);
            q2a = fmaf(v.z, A1[4 * jj + 2], q2a);
            q3a = fmaf(v.w, A1[4 * jj + 3], q3a);
        }
        const float* eb = swb_s + (t - 1) * KK;
        a0 = ((p0a + p1a) + (p2a + p3a)) * eb[lane];
        a1 = ((q0a + q1a) + (q2a + q3a)) * eb[lane + 32];
        buf ^= 1;
    }

    float contrib = a0 * __expf(WA[lane * KK + EOS_T])
                  + a1 * __expf(WA[(lane + 32) * KK + EOS_T]);
#pragma unroll
    for (int o = 16; o > 0; o >>= 1) contrib += __shfl_down_sync(0xffffffffu, contrib, o);

    if (lane == 0)
        out[b] = tagged - (__logf(contrib) + 126.0f * LOG64);
}

// ---------------------------------------------------------------------------
// Inputs: WA[64*64] f32, ThetaB[64*512] f32, E[100000*512] f32,
//         words[512*128] i32, tags[512*128] i32  ->  out f32[512]
// ---------------------------------------------------------------------------
extern "C" void kernel_launch(void* const* d_in, const int* in_sizes, int n_in,
                              void* d_out, int out_size)
{
    const float* WA     = (const float*)d_in[0];
    const float* ThetaB = (const float*)d_in[1];
    const float* E      = (const float*)d_in[2];
    const int*   words  = (const int*)d_in[3];
    const int*   tags   = (const int*)d_in[4];
    float*       out    = (float*)d_out;

    // emit split into 3 sub-launches (profiling visibility + same total work)
    emit_kernel<<<342, 256>>>(0,   ThetaB, E, words);
    emit_kernel<<<342, 256>>>(342, ThetaB, E, words);
    emit_kernel<<<340, 256>>>(684, ThetaB, E, words);
    forward_kernel<<<512, 32>>>(WA, tags, out);
}

// round 12
// speedup vs baseline: 1.0272x; 1.0272x over previous
#include <cuda_runtime.h>
#include <cuda_bf16.h>
#include <math.h>
#include <stdint.h>

// Problem constants
#define KK    64
#define DD    512
#define TT    128
#define BB    512
#define BOS_T 63
#define EOS_T 62
#define LOG64 4.158883083359672f

#define ABUF  17408           // one bf16 tile buffer: 64 rows x 272B
// dynamic SMEM layout: A[0], A[1], B[0], B[1]
#define OFF_B (2 * ABUF)
#define SMEM_EMIT (4 * ABUF)  // 69632 B

// Emission probabilities exp(wb)/64 (cols 62,63 zeroed): [seq][t][k] f32 = 16 MB
__device__ float g_swb[(size_t)BB * TT * KK];

__device__ __forceinline__ uint32_t pk(float a, float b) {
    __nv_bfloat162 h = __floats2bfloat162_rn(a, b);
    return *reinterpret_cast<uint32_t*>(&h);
}

__device__ __forceinline__ void mma16816(float* c, uint32_t a0, uint32_t a1,
                                         uint32_t a2, uint32_t a3,
                                         uint32_t b0, uint32_t b1) {
    asm volatile(
        "mma.sync.aligned.m16n8k16.row.col.f32.bf16.bf16.f32 "
        "{%0,%1,%2,%3}, {%4,%5,%6,%7}, {%8,%9}, {%0,%1,%2,%3};"
        : "+f"(c[0]), "+f"(c[1]), "+f"(c[2]), "+f"(c[3])
        : "r"(a0), "r"(a1), "r"(a2), "r"(a3), "r"(b0), "r"(b1));
}

__device__ __forceinline__ void ldsm4(uint32_t& r0, uint32_t& r1,
                                      uint32_t& r2, uint32_t& r3, uint32_t addr) {
    asm volatile("ldmatrix.sync.aligned.m8n8.x4.shared.b16 {%0,%1,%2,%3}, [%4];"
                 : "=r"(r0), "=r"(r1), "=r"(r2), "=r"(r3) : "r"(addr));
}

// ---------------------------------------------------------------------------
// Kernel 1: emission, warp-specialized producer/consumer pipeline.
// 1024 CTAs = (seq b, t-half h). M=64 t-rows x N=64 tags, K=512 in 4 chunks.
// Warps 4-7: gather E + ThetaB chunk c -> bf16 SMEM ring buf[c&1].
// Warps 0-3: ldmatrix + MMA on chunk c from buf[c&1] after matched sync.
// Barrier pairing (4 matched __syncthreads on both paths):
//   producers: write chunk c, then sync #c+1
//   consumers: sync #c+1, then MMA chunk c (overlaps producers' chunk c+1);
//   buf[c&1] reuse by chunk c+2 is fenced by sync #c+2 (after MMA of c).
// Epilogue (consumers): exp(wb)/64, mask cols 62/63 -> g_swb.
// ---------------------------------------------------------------------------
__global__ __launch_bounds__(256, 3)
void emit_kernel(const float* __restrict__ ThetaB,
                 const float* __restrict__ E,
                 const int*   __restrict__ words)
{
    extern __shared__ char sm[];

    const int blk = blockIdx.x;
    const int b = blk >> 1, h = blk & 1;
    const int tid  = threadIdx.x;
    const int wid  = tid >> 5, lane = tid & 31;

    const uint32_t base = (uint32_t)__cvta_generic_to_shared(sm);

    if (wid >= 4) {
        // ---------------- producers ----------------
        const int p    = tid - 128;
        const int row  = p >> 1, half = p & 1;
        const int word = words[b * TT + h * 64 + row];
        const float4* ep = (const float4*)(E + (size_t)word * DD);
        const float4* tp = (const float4*)(ThetaB + row * DD);
        char* Arow = sm + row * 272 + half * 128;
        char* Brow = sm + OFF_B + row * 272 + half * 128;

        for (int c = 0; c < 4; ++c) {
            const int bo = (c & 1) * ABUF;
            const float4* e4 = ep + c * 32 + half * 16;
            const float4* t4 = tp + c * 32 + half * 16;
            // two groups of 8 float4 each (MLP 8, bounded regs)
#pragma unroll
            for (int grp = 0; grp < 2; ++grp) {
                float4 er[8];
#pragma unroll
                for (int j = 0; j < 8; ++j) er[j] = e4[grp * 8 + j];
#pragma unroll
                for (int jj = 0; jj < 4; ++jj) {
                    float4 f0 = er[2 * jj], f1 = er[2 * jj + 1];
                    *(uint4*)(Arow + bo + grp * 64 + jj * 16) =
                        make_uint4(pk(f0.x, f0.y), pk(f0.z, f0.w),
                                   pk(f1.x, f1.y), pk(f1.z, f1.w));
                }
                float4 tr[8];
#pragma unroll
                for (int j = 0; j < 8; ++j) tr[j] = t4[grp * 8 + j];
#pragma unroll
                for (int jj = 0; jj < 4; ++jj) {
                    float4 g0 = tr[2 * jj], g1 = tr[2 * jj + 1];
                    *(uint4*)(Brow + bo + grp * 64 + jj * 16) =
                        make_uint4(pk(g0.x, g0.y), pk(g0.z, g0.w),
                                   pk(g1.x, g1.y), pk(g1.z, g1.w));
                }
            }
            __syncthreads();     // sync #c+1: chunk c published
        }
        // producers done: 4 barriers total, matching consumers
    } else {
        // ---------------- consumers ----------------
        const int g  = lane >> 2, t4 = lane & 3;
        const int m0 = wid * 16;

        const uint32_t aA = base + (uint32_t)((m0 + (lane & 15)) * 272
                          + ((lane >> 4) & 1) * 16);
        const uint32_t aBc = base + OFF_B
                          + (uint32_t)((((lane >> 4) & 1) * 8 + (lane & 7)) * 272
                          + ((lane >> 3) & 1) * 16);

        float acc[8][4];
#pragma unroll
        for (int nt = 0; nt < 8; ++nt)
#pragma unroll
            for (int r = 0; r < 4; ++r) acc[nt][r] = 0.f;

        for (int c = 0; c < 4; ++c) {
            __syncthreads();                    // sync #c+1: chunk c ready
            const uint32_t bo = (c & 1) * ABUF;
#pragma unroll
            for (int s = 0; s < 8; ++s) {
                uint32_t a0, a1, a2, a3;
                ldsm4(a0, a1, a2, a3, aA + bo + s * 32);
#pragma unroll
                for (int i = 0; i < 4; ++i) {
                    uint32_t b0, b1, b2, b3;
                    ldsm4(b0, b1, b2, b3, aBc + bo + i * (16 * 272) + s * 32);
                    mma16816(acc[2 * i],     a0, a1, a2, a3, b0, b1);
                    mma16816(acc[2 * i + 1], a0, a1, a2, a3, b2, b3);
                }
            }
        }

        // epilogue: exp/64, mask cols 62/63, write f32
        const float inv = 1.0f / 64.0f;
        float* obase = g_swb + (size_t)b * TT * KK;
        const int t0 = h * 64 + m0 + g, t1 = t0 + 8;
#pragma unroll
        for (int nt = 0; nt < 8; ++nt) {
            const int col = nt * 8 + t4 * 2;
            const bool msk = (col == EOS_T);
            float2 v0, v1;
            v0.x = msk ? 0.f : __expf(acc[nt][0]) * inv;
            v0.y = msk ? 0.f : __expf(acc[nt][1]) * inv;
            v1.x = msk ? 0.f : __expf(acc[nt][2]) * inv;
            v1.y = msk ? 0.f : __expf(acc[nt][3]) * inv;
            *(float2*)(obase + t0 * KK + col) = v0;
            *(float2*)(obase + t1 * KK + col) = v1;
        }
    }
}

// ---------------------------------------------------------------------------
// Kernel 2: 2 warps (64 threads) per sequence. Each thread owns one output k
// with its full A column in registers; one __syncthreads per step.
// ---------------------------------------------------------------------------
__global__ __launch_bounds__(64)
void forward_kernel(const float* __restrict__ WA,
                    const int*   __restrict__ tags,
                    float*       __restrict__ out)
{
    __shared__ __align__(16) float swb_s[126 * KK];   // rows t=1..126
    __shared__ __align__(16) float sal[2][KK];
    __shared__ float sred[4];

    const int k    = threadIdx.x;      // 0..63
    const int wid  = k >> 5, lane = k & 31;
    const int b    = blockIdx.x;

    // stage: pure copy of rows 1..126
    {
        const float4* src = (const float4*)(g_swb + (size_t)b * TT * KK + KK);
        float4* dst = (float4*)swb_s;
        for (int i = k; i < 126 * 16; i += 64) dst[i] = src[i];
    }

    // full A column for this k
    float A[KK];
#pragma unroll
    for (int j = 0; j < KK; ++j) A[j] = __expf(WA[j * KK + k]);
    __syncthreads();

    // tagged closed form (t strided by 64 over 1..126)
    float tagc = 0.f;
    for (int t = k + 1; t <= 126; t += 64) {
        const int ct = tags[b * TT + t];
        const int pt = (t == 1) ? BOS_T : tags[b * TT + t - 1];
        tagc += __logf(swb_s[(t - 1) * KK + ct]) + LOG64 + WA[pt * KK + ct];
    }
    if (k == 63) tagc += WA[tags[b * TT + 126] * KK + EOS_T];
#pragma unroll
    for (int o = 16; o > 0; o >>= 1) tagc += __shfl_down_sync(0xffffffffu, tagc, o);
    if (lane == 0) sred[wid] = tagc;

    // forward recursion
    float alph = A[BOS_T] * swb_s[k];              // t=1 row at offset 0
    int buf = 0;
    for (int t = 2; t <= 126; ++t) {
        sal[buf][k] = alph;
        __syncthreads();
        const float4* av = (const float4*)sal[buf];
        float s0 = 0.f, s1 = 0.f, s2 = 0.f, s3 = 0.f;
#pragma unroll
        for (int jj = 0; jj < 16; ++jj) {
            const float4 v = av[jj];
            s0 = fmaf(v.x, A[4 * jj + 0], s0);
            s1 = fmaf(v.y, A[4 * jj + 1], s1);
            s2 = fmaf(v.z, A[4 * jj + 2], s2);
            s3 = fmaf(v.w, A[4 * jj + 3], s3);
        }
        alph = ((s0 + s1) + (s2 + s3)) * swb_s[(t - 1) * KK + k];
        buf ^= 1;
        // next iteration writes the other buffer; its __syncthreads fences
        // this iteration's reads before wraparound.
    }

    float contrib = alph * __expf(WA[k * KK + EOS_T]);
#pragma unroll
    for (int o = 16; o > 0; o >>= 1) contrib += __shfl_down_sync(0xffffffffu, contrib, o);
    if (lane == 0) sred[2 + wid] = contrib;
    __syncthreads();

    if (k == 0)
        out[b] = (sred[0] + sred[1])
               - (__logf(sred[2] + sred[3]) + 126.0f * LOG64);
}

// ---------------------------------------------------------------------------
// Inputs: WA[64*64] f32, ThetaB[64*512] f32, E[100000*512] f32,
//         words[512*128] i32, tags[512*128] i32  ->  out f32[512]
// ---------------------------------------------------------------------------
extern "C" void kernel_launch(void* const* d_in, const int* in_sizes, int n_in,
                              void* d_out, int out_size)
{
    const float* WA     = (const float*)d_in[0];
    const float* ThetaB = (const float*)d_in[1];
    const float* E      = (const float*)d_in[2];
    const int*   words  = (const int*)d_in[3];
    const int*   tags   = (const int*)d_in[4];
    float*       out    = (float*)d_out;

    static int attr_done = 0;
    if (!attr_done) {
        cudaFuncSetAttribute(emit_kernel,
                             cudaFuncAttributeMaxDynamicSharedMemorySize, SMEM_EMIT);
        attr_done = 1;
    }
    emit_kernel<<<1024, 256, SMEM_EMIT>>>(ThetaB, E, words);
    forward_kernel<<<512, 64>>>(WA, tags, out);
}